// round 16
// baseline (speedup 1.0000x reference)
#include <cuda_runtime.h>
#include <cuda_fp16.h>
#include <cstdint>

// ---------------- problem constants ----------------
#define T_TOK 8192
#define D_DIM 512
#define F_DIM 1024
#define E_NUM 8
#define K_TOP 2
#define NSLOT (T_TOK * K_TOP)      // 16384 slots
#define MT_MAX 128
#define NW2SL 512                   // W2 convert slices (ride on first 512 p1 tiles)

// ---------------- GEMM tiling ----------------
#define BM 128
#define BN 128
#define BK 64
#define NSTAGE 3
#define NTHREADS 256                // 8 warps: 2(m) x 4(n) of 64x32
#define NCTA 304                    // persistent grid: 2 CTAs x 152 SMs (GB300)
#define A_STAGE_BYTES (BM * 128)    // 16 KB
#define B_STAGE_BYTES (BK * 256)    // 16 KB (pre-swizzled 256B rows)
#define SMEM_BYTES (NSTAGE * (A_STAGE_BYTES + B_STAGE_BYTES))   // 96 KB
#define KT1 (D_DIM / BK)            // 8
#define KT2 (F_DIM / BK)            // 16

// ---------------- device scratch (self-resetting; statics cover first run) ----------------
__device__ int      g_slots[E_NUM][NSLOT];
__device__ int      g_cnt[E_NUM];                            // reset by last GEMM CTA
__device__ int      g_work = NCTA;                           // reset by last GEMM CTA
__device__ int      g_exit;                                  // reset by last GEMM CTA
__device__ unsigned g_ready[E_NUM * MT_MAX];                 // reset by 4th p2 consumer
__device__ unsigned g_done[E_NUM * MT_MAX];                  // reset by 4th p2 consumer
__device__ unsigned g_w2done;                                // reset by last GEMM CTA
__device__ __half   g_Xh[(size_t)T_TOK * D_DIM];             // 8 MB
__device__ __half   g_H[(size_t)NSLOT * F_DIM];              // 32 MB
__device__ __half   g_W1p[(size_t)E_NUM * D_DIM * F_DIM];    // 8 MB packed+swizzled
__device__ __half   g_W2p[(size_t)E_NUM * F_DIM * D_DIM];    // 8 MB (converted in-GEMM)

// ---------------- PTX helpers ----------------
__device__ __forceinline__ uint32_t smem_u32(const void* p) {
    uint32_t a;
    asm("{ .reg .u64 t; cvta.to.shared.u64 t, %1; cvt.u32.u64 %0, t; }" : "=r"(a) : "l"(p));
    return a;
}
__device__ __forceinline__ void cp_async16(uint32_t dst, const void* src) {
    asm volatile("cp.async.cg.shared.global [%0], [%1], 16;\n" :: "r"(dst), "l"(src));
}
__device__ __forceinline__ void cp_commit() { asm volatile("cp.async.commit_group;\n"); }
template <int N>
__device__ __forceinline__ void cp_wait() {
    asm volatile("cp.async.wait_group %0;\n" :: "n"(N) : "memory");
}
__device__ __forceinline__ void cp_bulk(uint32_t dst, const void* src,
                                        uint32_t bytes, uint32_t mbar) {
    asm volatile("cp.async.bulk.shared::cta.global.mbarrier::complete_tx::bytes "
                 "[%0], [%1], %2, [%3];"
                 :: "r"(dst), "l"(src), "r"(bytes), "r"(mbar) : "memory");
}
__device__ __forceinline__ void mbar_init(uint32_t addr, uint32_t cnt) {
    asm volatile("mbarrier.init.shared.b64 [%0], %1;" :: "r"(addr), "r"(cnt) : "memory");
}
__device__ __forceinline__ void mbar_expect_tx(uint32_t addr, uint32_t bytes) {
    asm volatile("mbarrier.arrive.expect_tx.shared.b64 _, [%0], %1;"
                 :: "r"(addr), "r"(bytes) : "memory");
}
__device__ __forceinline__ void mbar_wait(uint32_t addr, uint32_t phase) {
    asm volatile(
        "{\n\t.reg .pred P;\n"
        "W%=:\n\t"
        "mbarrier.try_wait.parity.shared::cta.b64 P, [%0], %1, 0x989680;\n\t"
        "@!P bra W%=;\n"
        "}" :: "r"(addr), "r"(phase) : "memory");
}
__device__ __forceinline__ void ldsm_x4(uint32_t* r, uint32_t addr) {
    asm volatile("ldmatrix.sync.aligned.m8n8.x4.shared.b16 {%0,%1,%2,%3}, [%4];"
                 : "=r"(r[0]), "=r"(r[1]), "=r"(r[2]), "=r"(r[3]) : "r"(addr));
}
__device__ __forceinline__ void ldsm_x4_trans(uint32_t* r, uint32_t addr) {
    asm volatile("ldmatrix.sync.aligned.m8n8.x4.trans.shared.b16 {%0,%1,%2,%3}, [%4];"
                 : "=r"(r[0]), "=r"(r[1]), "=r"(r[2]), "=r"(r[3]) : "r"(addr));
}
__device__ __forceinline__ void mma_fp16(float c[4], const uint32_t a[4],
                                         uint32_t b0, uint32_t b1) {
    asm volatile(
        "mma.sync.aligned.m16n8k16.row.col.f32.f16.f16.f32 "
        "{%0,%1,%2,%3},{%4,%5,%6,%7},{%8,%9},{%0,%1,%2,%3};\n"
        : "+f"(c[0]), "+f"(c[1]), "+f"(c[2]), "+f"(c[3])
        : "r"(a[0]), "r"(a[1]), "r"(a[2]), "r"(a[3]), "r"(b0), "r"(b1));
}
__device__ __forceinline__ void red_add_v2(float* p, float v0, float v1) {
    asm volatile("red.relaxed.gpu.global.add.v2.f32 [%0], {%1,%2};"
                 :: "l"(p), "f"(v0), "f"(v1) : "memory");
}
__device__ __forceinline__ void ready_release_inc(unsigned* p) {
    asm volatile("red.release.gpu.global.add.u32 [%0], 1;" :: "l"(p) : "memory");
}
__device__ __forceinline__ unsigned ready_acquire_ld(const unsigned* p) {
    unsigned v;
    asm volatile("ld.acquire.gpu.global.u32 %0, [%1];" : "=r"(v) : "l"(p) : "memory");
    return v;
}
__device__ __forceinline__ uint32_t f22h2(float a, float b) {
    __half2 h = __floats2half2_rn(a, b);
    return *reinterpret_cast<uint32_t*>(&h);
}

// tanh-approx gelu (same formula as jax): gelu(x) = x - x/(E+1), E = exp(2z)
__device__ __forceinline__ float gelu_fast(float x) {
    float z = 0.7978845608028654f * fmaf(0.044715f * x, x * x, x);
    float E;
    asm("ex2.approx.f32 %0, %1;" : "=f"(E) : "f"(z * 2.8853900817779268f));
    float r;
    asm("rcp.approx.f32 %0, %1;" : "=f"(r) : "f"(E + 1.0f));
    return x - x * r;
}

// ---------------- fused prep+route (W2 conversion moved into GEMM) ----------------
#define NX4 (T_TOK * D_DIM / 4)                 // 1,048,576
#define NWC (E_NUM * D_DIM * F_DIM / 8)         // 524,288 16B-chunks per weight
#define PREP_TOTAL (NSLOT + NX4 + NWC + NX4)
__global__ void prep_kernel(const float* __restrict__ hidden,
                            const int*   __restrict__ idx,
                            const float* __restrict__ W1,
                            float* __restrict__ out) {
    const int gi = blockIdx.x * blockDim.x + threadIdx.x;
    if (gi >= PREP_TOTAL) return;
    if (gi < NSLOT) {
        const int e = idx[gi];
        const int p = atomicAdd(&g_cnt[e], 1);
        g_slots[e][p] = gi;
        return;
    }
    const int i = gi - NSLOT;
    if (i < NX4) {
        float4 v = ((const float4*)hidden)[i];
        ((__half2*)g_Xh)[2 * i + 0] = __floats2half2_rn(v.x, v.y);
        ((__half2*)g_Xh)[2 * i + 1] = __floats2half2_rn(v.z, v.w);
    } else if (i < NX4 + NWC) {
        // W1: KDIM=512, NT=8
        const int j  = i - NX4;
        const int e  = j >> 16;
        const int c  = j & 0xFFFF;
        const int nt = c >> 13;
        const int k  = (c >> 4) & 511;
        const int p  = c & 15;
        const int ch = p ^ (k & 7);
        const float* s = W1 + ((size_t)(e * 512 + k)) * F_DIM + nt * 128 + ch * 8;
        float4 v0 = *(const float4*)s, v1 = *(const float4*)(s + 4);
        uint4 o;
        o.x = f22h2(v0.x, v0.y); o.y = f22h2(v0.z, v0.w);
        o.z = f22h2(v1.x, v1.y); o.w = f22h2(v1.z, v1.w);
        *(uint4*)(g_W1p + ((size_t)((e * 8 + nt) * 512 + k)) * 128 + p * 8) = o;
    } else {
        int j = i - NX4 - NWC;
        ((float4*)out)[j] = make_float4(0.f, 0.f, 0.f, 0.f);
    }
}

// ---------------- W2 convert slice (1024 chunks; rides on a p1 tile) ----------------
__device__ __forceinline__ void convert_w2_slice(int sl, const float* __restrict__ W2,
                                                 int tid) {
    #pragma unroll
    for (int it = 0; it < 4; ++it) {
        const int j  = sl * 1024 + it * NTHREADS + tid;   // global W2 chunk index
        const int e  = j >> 16;
        const int c  = j & 0xFFFF;
        const int nt = c >> 14;
        const int k  = (c >> 4) & 1023;
        const int p  = c & 15;
        const int ch = p ^ (k & 7);
        const float* s = W2 + ((size_t)(e * 1024 + k)) * D_DIM + nt * 128 + ch * 8;
        float4 v0 = *(const float4*)s, v1 = *(const float4*)(s + 4);
        uint4 o;
        o.x = f22h2(v0.x, v0.y); o.y = f22h2(v0.z, v0.w);
        o.z = f22h2(v1.x, v1.y); o.w = f22h2(v1.z, v1.w);
        *(uint4*)(g_W2p + ((size_t)((e * 4 + nt) * 1024 + k)) * 128 + p * 8) = o;
    }
    __threadfence();
    __syncthreads();
    if (tid == 0) ready_release_inc(&g_w2done);
}

// ---------------- one pipeline load step ----------------
// Dependency spins happen BEFORE the B bulk issue (B = g_W2p guarded for p2).
__device__ __forceinline__ void load_step(
    int phase, const int* __restrict__ srow, const __half* __restrict__ Wtile,
    int kt, int pos, uint32_t sbase, uint32_t bbase0, uint64_t* s_mbar,
    int tid, const unsigned* ready_ptr, bool w2_guard)
{
    const int s = pos % NSTAGE;
    const int k0 = kt * BK;
    if (ready_ptr) {
        while (ready_acquire_ld(ready_ptr) < (unsigned)(F_DIM / BN)) __nanosleep(64);
    }
    if (w2_guard) {
        while (ready_acquire_ld(&g_w2done) < (unsigned)NW2SL) __nanosleep(64);
    }
    if (tid == 0) {
        const uint32_t mb = smem_u32(&s_mbar[s]);
        mbar_expect_tx(mb, B_STAGE_BYTES);
        cp_bulk(bbase0 + (uint32_t)s * B_STAGE_BYTES,
                Wtile + (size_t)k0 * 128, B_STAGE_BYTES, mb);
    }
    const uint32_t abuf = sbase + (uint32_t)s * A_STAGE_BYTES;
    #pragma unroll
    for (int it = 0; it < 4; ++it) {
        const int c  = tid + it * NTHREADS;
        const int r  = c >> 3;
        const int ch = c & 7;
        const int slot = srow[r];
        const __half* asrc = (phase == 1)
            ? g_Xh + (size_t)(slot >> 1) * D_DIM + k0 + ch * 8
            : g_H  + (size_t)slot * F_DIM        + k0 + ch * 8;
        cp_async16(abuf + (uint32_t)(r * 128 + ((ch ^ (r & 7)) << 4)), asrc);
    }
    cp_commit();
}

// ---------------- fused persistent GEMM + amortized W2 conversion ----------------
__global__ __launch_bounds__(NTHREADS, 2)
void moe_gemm_fused(const float* __restrict__ b1,
                    const float* __restrict__ b2,
                    const float* __restrict__ wts,
                    const float* __restrict__ W2,
                    float* __restrict__ out) {
    extern __shared__ __align__(1024) char dsm[];
    const uint32_t sbase  = smem_u32(dsm);
    const uint32_t bbase0 = sbase + NSTAGE * A_STAGE_BYTES;

    __shared__ int      s_srow[2][BM];
    __shared__ uint64_t s_mbar[NSTAGE];
    __shared__ int      s_nxt;
    __shared__ int      s_tcnt[E_NUM], s_tb1[E_NUM];
    __shared__ int      s_p1tot;

    const int tid  = threadIdx.x;
    const int wid  = tid >> 5;
    const int lane = tid & 31;
    const int wm = (wid & 1) * 64;
    const int wn = (wid >> 1) * 32;
    const int rA = lane & 15;
    const int cl = lane >> 4;

    if (tid == 0) {
        #pragma unroll
        for (int s = 0; s < NSTAGE; ++s) mbar_init(smem_u32(&s_mbar[s]), 1);
        int acc = 0;
        #pragma unroll
        for (int e = 0; e < E_NUM; ++e) {
            s_tb1[e] = acc;
            int c = g_cnt[e];
            s_tcnt[e] = c;
            acc += ((c + BM - 1) >> 7) * (F_DIM / BN);
        }
        s_p1tot = acc;
    }
    __syncthreads();
    const int p1_total = s_p1tot;          // always >= 1024 > NW2SL
    const int total    = p1_total + (p1_total >> 1);

    // loop-invariant LDSM fragment offsets
    uint32_t offA[4][4], offB[4][2];
    #pragma unroll
    for (int mf = 0; mf < 4; ++mf) {
        const int r = wm + mf * 16 + rA;
        #pragma unroll
        for (int ks = 0; ks < 4; ++ks)
            offA[mf][ks] = (uint32_t)(r * 128 + (((ks * 2 + cl) ^ (r & 7)) << 4));
    }
    #pragma unroll
    for (int ks = 0; ks < 4; ++ks) {
        const int rb = ks * 16 + rA;
        #pragma unroll
        for (int nf16 = 0; nf16 < 2; ++nf16)
            offB[ks][nf16] = (uint32_t)(rb * 256 +
                              ((((wn >> 3) + nf16 * 2 + cl) ^ (rb & 7)) << 4));
    }

    auto decode = [&](int t, int& phase, int& e, int& cnt, int& m0, int& nt) {
        if (t < p1_total) {
            phase = 1; e = 0;
            #pragma unroll
            for (int q = 1; q < E_NUM; ++q) if (t >= s_tb1[q]) e = q;
            const int local = t - s_tb1[e];
            cnt = s_tcnt[e]; m0 = (local >> 3) << 7; nt = local & 7;
        } else {
            phase = 2; const int t2 = t - p1_total; e = 0;
            #pragma unroll
            for (int q = 1; q < E_NUM; ++q) if (t2 >= (s_tb1[q] >> 1)) e = q;
            const int local = t2 - (s_tb1[e] >> 1);
            cnt = s_tcnt[e]; m0 = (local >> 2) << 7; nt = local & 3;
        }
    };
    auto wptr = [&](int phase, int e, int nt) -> const __half* {
        return (phase == 1)
            ? g_W1p + (size_t)(e * 8 + nt) * D_DIM * 128
            : g_W2p + (size_t)(e * 4 + nt) * F_DIM * 128;
    };

    int ct = (int)blockIdx.x;               // current tile queue index
    int cphase, ce, ccnt, cm0, cnt_i;
    decode(ct, cphase, ce, ccnt, cm0, cnt_i);
    const __half* cW = wptr(cphase, ce, cnt_i);
    int curbuf = 0;

    if (tid < BM) s_srow[0][tid] = g_slots[ce][min(cm0 + tid, ccnt - 1)];
    __syncthreads();

    // static first claim is always p1 (blockIdx < 304 <= p1_total): no guards
    load_step(cphase, s_srow[0], cW, 0, 0, sbase, bbase0, s_mbar, tid, nullptr, false);
    load_step(cphase, s_srow[0], cW, 1, 1, sbase, bbase0, s_mbar, tid, nullptr, false);

    int rc = 0;

    for (;;) {
        const int KT = (cphase == 1) ? KT1 : KT2;
        int nphase = 0, ne = 0, ncnt = 0, nm0 = 0, nnt = 0, nT = 0;
        bool have_nxt = false;
        const __half* nW = nullptr;

        float acc[4][4][4];
        #pragma unroll
        for (int i = 0; i < 4; ++i)
            #pragma unroll
            for (int j = 0; j < 4; ++j)
                #pragma unroll
                for (int r = 0; r < 4; ++r) acc[i][j][r] = 0.f;

        for (int kt = 0; kt < KT; ++kt) {
            const int s = rc % NSTAGE;
            cp_wait<1>();
            mbar_wait(smem_u32(&s_mbar[s]), (rc / NSTAGE) & 1);
            __syncthreads();

            if (kt == 0) {
                if (tid == 0) s_nxt = atomicAdd(&g_work, 1);
            } else if (kt == 1) {
                const int t = s_nxt;
                have_nxt = t < total;
                if (have_nxt) {
                    nT = t;
                    decode(t, nphase, ne, ncnt, nm0, nnt);
                    nW = wptr(nphase, ne, nnt);
                    if (tid < BM)
                        s_srow[curbuf ^ 1][tid] = g_slots[ne][min(nm0 + tid, ncnt - 1)];
                }
            }

            const uint32_t abuf = sbase + (uint32_t)s * A_STAGE_BYTES;
            const uint32_t bbuf = bbase0 + (uint32_t)s * B_STAGE_BYTES;

            #pragma unroll
            for (int ks = 0; ks < BK / 16; ++ks) {
                uint32_t af[4][4];
                #pragma unroll
                for (int mf = 0; mf < 4; ++mf)
                    ldsm_x4(af[mf], abuf + offA[mf][ks]);
                uint32_t bf[2][4];
                #pragma unroll
                for (int nf16 = 0; nf16 < 2; ++nf16)
                    ldsm_x4_trans(bf[nf16], bbuf + offB[ks][nf16]);
                #pragma unroll
                for (int mf = 0; mf < 4; ++mf)
                    #pragma unroll
                    for (int nf = 0; nf < 4; ++nf) {
                        const int g = nf >> 1;
                        const int h = (nf & 1) * 2;
                        mma_fp16(acc[mf][nf], af[mf], bf[g][h], bf[g][h + 1]);
                    }
            }

            // produce ring position rc+2 (after compute — R10 ordering)
            const int j2 = kt + 2;
            if (j2 < KT) {
                load_step(cphase, s_srow[curbuf], cW, j2, rc + 2,
                          sbase, bbase0, s_mbar, tid, nullptr, false);
            } else if (have_nxt && !(cphase == 1 && nphase == 2)) {
                const bool first = (j2 - KT) == 0;
                const unsigned* rp = (nphase == 2 && first)
                    ? &g_ready[ne * MT_MAX + (nm0 >> 7)] : nullptr;
                load_step(nphase, s_srow[curbuf ^ 1], nW, j2 - KT, rc + 2,
                          sbase, bbase0, s_mbar, tid, rp,
                          (nphase == 2 && first));
            } else {
                cp_commit();   // empty group keeps cp accounting uniform
            }
            ++rc;
        }

        // ---------------- epilogue ----------------
        {
            const int NDIM = (cphase == 1) ? F_DIM : D_DIM;
            const int n0   = cnt_i * BN;
            const float* __restrict__ brow =
                ((cphase == 1) ? b1 : b2) + (size_t)ce * NDIM + n0;
            const int rbase = wm + (lane >> 2);
            const int cbase = wn + 2 * (lane & 3);
            #pragma unroll
            for (int mf = 0; mf < 4; ++mf) {
                #pragma unroll
                for (int half = 0; half < 2; ++half) {
                    const int rloc = rbase + mf * 16 + half * 8;
                    const int gm   = cm0 + rloc;
                    if (gm < ccnt) {
                        const int slot = s_srow[curbuf][rloc];
                        if (cphase == 1) {
                            __half* __restrict__ orow = g_H + (size_t)slot * F_DIM + n0;
                            #pragma unroll
                            for (int nf = 0; nf < 4; ++nf) {
                                const int col = cbase + nf * 8;
                                const float2 bv = *(const float2*)(brow + col);
                                float v0 = gelu_fast(acc[mf][nf][half * 2 + 0] + bv.x);
                                float v1 = gelu_fast(acc[mf][nf][half * 2 + 1] + bv.y);
                                *(__half2*)(orow + col) = __floats2half2_rn(v0, v1);
                            }
                        } else {
                            const float w = __ldg(wts + slot);
                            float* __restrict__ orow =
                                out + (size_t)(slot >> 1) * D_DIM + n0;
                            #pragma unroll
                            for (int nf = 0; nf < 4; ++nf) {
                                const int col = cbase + nf * 8;
                                const float2 bv = *(const float2*)(brow + col);
                                float v0 = (acc[mf][nf][half * 2 + 0] + bv.x) * w;
                                float v1 = (acc[mf][nf][half * 2 + 1] + bv.y) * w;
                                red_add_v2(orow + col, v0, v1);
                            }
                        }
                    }
                }
            }
        }

        if (cphase == 1) {
            __threadfence();
            __syncthreads();
            if (tid == 0) ready_release_inc(&g_ready[ce * MT_MAX + (cm0 >> 7)]);
            // amortized W2 conversion: slice ct rides on p1 tile ct (< NW2SL)
            if (ct < NW2SL) convert_w2_slice(ct, W2, tid);
        } else {
            // per-entry self-reset by the 4th (last) consumer
            if (tid == 0) {
                const int ridx = ce * MT_MAX + (cm0 >> 7);
                if (atomicAdd(&g_done[ridx], 1u) == 3u) {
                    g_ready[ridx] = 0u;
                    g_done[ridx]  = 0u;
                }
            }
        }

        if (!have_nxt) break;

        if (cphase == 1 && nphase == 2) {
            const unsigned* rp = &g_ready[ne * MT_MAX + (nm0 >> 7)];
            load_step(nphase, s_srow[curbuf ^ 1], nW, 0, rc,
                      sbase, bbase0, s_mbar, tid, rp, true);
            load_step(nphase, s_srow[curbuf ^ 1], nW, 1, rc + 1,
                      sbase, bbase0, s_mbar, tid, nullptr, false);
        }

        ct = nT;
        cphase = nphase; ce = ne; ccnt = ncnt; cm0 = nm0; cnt_i = nnt;
        cW = nW; curbuf ^= 1;
    }

    // self-reset of g_cnt / g_work / g_w2done for the next graph replay.
    __syncthreads();
    if (tid == 0) {
        if (atomicAdd(&g_exit, 1) == NCTA - 1) {
            #pragma unroll
            for (int e = 0; e < E_NUM; ++e) g_cnt[e] = 0;
            g_w2done = 0u;
            g_work = NCTA;
            g_exit = 0;
        }
    }
}

// ---------------- launch (2 kernels) ----------------
extern "C" void kernel_launch(void* const* d_in, const int* in_sizes, int n_in,
                              void* d_out, int out_size) {
    const float* hidden = (const float*)d_in[0];
    const int*   idx    = (const int*)d_in[1];
    const float* wts    = (const float*)d_in[2];
    const float* W1     = (const float*)d_in[3];
    const float* b1     = (const float*)d_in[4];
    const float* W2     = (const float*)d_in[5];
    const float* b2     = (const float*)d_in[6];
    float*       out    = (float*)d_out;
    (void)in_sizes; (void)n_in; (void)out_size;

    cudaFuncSetAttribute(moe_gemm_fused, cudaFuncAttributeMaxDynamicSharedMemorySize, SMEM_BYTES);

    prep_kernel<<<(PREP_TOTAL + 255) / 256, 256>>>(hidden, idx, W1, out);
    moe_gemm_fused<<<NCTA, NTHREADS, SMEM_BYTES>>>(b1, b2, wts, W2, out);
}

// round 17
// speedup vs baseline: 1.0381x; 1.0381x over previous
#include <cuda_runtime.h>
#include <cuda_fp16.h>
#include <cstdint>

// ---------------- problem constants ----------------
#define T_TOK 8192
#define D_DIM 512
#define F_DIM 1024
#define E_NUM 8
#define K_TOP 2
#define NSLOT (T_TOK * K_TOP)      // 16384 slots
#define MT_MAX 128
#define NW2U 32                     // W2 convert units: 8 experts x 4 n-tiles

// ---------------- GEMM tiling ----------------
#define BM 128
#define BN 128
#define BK 64
#define NSTAGE 3
#define NTHREADS 256                // 8 warps: 2(m) x 4(n) of 64x32
#define NCTA 304                    // persistent grid: 2 CTAs x 152 SMs (GB300)
#define A_STAGE_BYTES (BM * 128)    // 16 KB
#define B_STAGE_BYTES (BK * 256)    // 16 KB (pre-swizzled 256B rows)
#define SMEM_BYTES (NSTAGE * (A_STAGE_BYTES + B_STAGE_BYTES))   // 96 KB
#define KT1 (D_DIM / BK)            // 8
#define KT2 (F_DIM / BK)            // 16

// ---------------- device scratch (self-resetting; statics cover first run) ----------------
__device__ int      g_slots[E_NUM][NSLOT];
__device__ int      g_cnt[E_NUM];                            // reset by last GEMM CTA
__device__ int      g_work = NCTA;                           // reset by last GEMM CTA
__device__ int      g_exit;                                  // reset by last GEMM CTA
__device__ unsigned g_ready[E_NUM * MT_MAX];                 // reset by 4th p2 consumer
__device__ unsigned g_done[E_NUM * MT_MAX];                  // reset by 4th p2 consumer
__device__ unsigned g_w2rdy[NW2U];                           // reset by last GEMM CTA
__device__ __half   g_Xh[(size_t)T_TOK * D_DIM];             // 8 MB
__device__ __half   g_H[(size_t)NSLOT * F_DIM];              // 32 MB
__device__ __half   g_W1p[(size_t)E_NUM * D_DIM * F_DIM];    // 8 MB packed+swizzled
__device__ __half   g_W2p[(size_t)E_NUM * F_DIM * D_DIM];    // 8 MB (converted in-GEMM)

// ---------------- PTX helpers ----------------
__device__ __forceinline__ uint32_t smem_u32(const void* p) {
    uint32_t a;
    asm("{ .reg .u64 t; cvta.to.shared.u64 t, %1; cvt.u32.u64 %0, t; }" : "=r"(a) : "l"(p));
    return a;
}
__device__ __forceinline__ void cp_async16(uint32_t dst, const void* src) {
    asm volatile("cp.async.cg.shared.global [%0], [%1], 16;\n" :: "r"(dst), "l"(src));
}
__device__ __forceinline__ void cp_commit() { asm volatile("cp.async.commit_group;\n"); }
template <int N>
__device__ __forceinline__ void cp_wait() {
    asm volatile("cp.async.wait_group %0;\n" :: "n"(N) : "memory");
}
__device__ __forceinline__ void cp_bulk(uint32_t dst, const void* src,
                                        uint32_t bytes, uint32_t mbar) {
    asm volatile("cp.async.bulk.shared::cta.global.mbarrier::complete_tx::bytes "
                 "[%0], [%1], %2, [%3];"
                 :: "r"(dst), "l"(src), "r"(bytes), "r"(mbar) : "memory");
}
__device__ __forceinline__ void mbar_init(uint32_t addr, uint32_t cnt) {
    asm volatile("mbarrier.init.shared.b64 [%0], %1;" :: "r"(addr), "r"(cnt) : "memory");
}
__device__ __forceinline__ void mbar_expect_tx(uint32_t addr, uint32_t bytes) {
    asm volatile("mbarrier.arrive.expect_tx.shared.b64 _, [%0], %1;"
                 :: "r"(addr), "r"(bytes) : "memory");
}
__device__ __forceinline__ void mbar_wait(uint32_t addr, uint32_t phase) {
    asm volatile(
        "{\n\t.reg .pred P;\n"
        "W%=:\n\t"
        "mbarrier.try_wait.parity.shared::cta.b64 P, [%0], %1, 0x989680;\n\t"
        "@!P bra W%=;\n"
        "}" :: "r"(addr), "r"(phase) : "memory");
}
__device__ __forceinline__ void ldsm_x4(uint32_t* r, uint32_t addr) {
    asm volatile("ldmatrix.sync.aligned.m8n8.x4.shared.b16 {%0,%1,%2,%3}, [%4];"
                 : "=r"(r[0]), "=r"(r[1]), "=r"(r[2]), "=r"(r[3]) : "r"(addr));
}
__device__ __forceinline__ void ldsm_x4_trans(uint32_t* r, uint32_t addr) {
    asm volatile("ldmatrix.sync.aligned.m8n8.x4.trans.shared.b16 {%0,%1,%2,%3}, [%4];"
                 : "=r"(r[0]), "=r"(r[1]), "=r"(r[2]), "=r"(r[3]) : "r"(addr));
}
__device__ __forceinline__ void mma_fp16(float c[4], const uint32_t a[4],
                                         uint32_t b0, uint32_t b1) {
    asm volatile(
        "mma.sync.aligned.m16n8k16.row.col.f32.f16.f16.f32 "
        "{%0,%1,%2,%3},{%4,%5,%6,%7},{%8,%9},{%0,%1,%2,%3};\n"
        : "+f"(c[0]), "+f"(c[1]), "+f"(c[2]), "+f"(c[3])
        : "r"(a[0]), "r"(a[1]), "r"(a[2]), "r"(a[3]), "r"(b0), "r"(b1));
}
__device__ __forceinline__ void red_add_v2(float* p, float v0, float v1) {
    asm volatile("red.relaxed.gpu.global.add.v2.f32 [%0], {%1,%2};"
                 :: "l"(p), "f"(v0), "f"(v1) : "memory");
}
__device__ __forceinline__ void ready_release_inc(unsigned* p) {
    asm volatile("red.release.gpu.global.add.u32 [%0], 1;" :: "l"(p) : "memory");
}
__device__ __forceinline__ unsigned ready_acquire_ld(const unsigned* p) {
    unsigned v;
    asm volatile("ld.acquire.gpu.global.u32 %0, [%1];" : "=r"(v) : "l"(p) : "memory");
    return v;
}
__device__ __forceinline__ uint32_t f22h2(float a, float b) {
    __half2 h = __floats2half2_rn(a, b);
    return *reinterpret_cast<uint32_t*>(&h);
}

// tanh-approx gelu (same formula as jax): gelu(x) = x - x/(E+1), E = exp(2z)
__device__ __forceinline__ float gelu_fast(float x) {
    float z = 0.7978845608028654f * fmaf(0.044715f * x, x * x, x);
    float E;
    asm("ex2.approx.f32 %0, %1;" : "=f"(E) : "f"(z * 2.8853900817779268f));
    float r;
    asm("rcp.approx.f32 %0, %1;" : "=f"(r) : "f"(E + 1.0f));
    return x - x * r;
}

// ---------------- fused prep+route (W2 conversion moved into GEMM) ----------------
#define NX4 (T_TOK * D_DIM / 4)                 // 1,048,576
#define NWC (E_NUM * D_DIM * F_DIM / 8)         // 524,288 16B-chunks per weight
#define PREP_TOTAL (NSLOT + NX4 + NWC + NX4)
__global__ void prep_kernel(const float* __restrict__ hidden,
                            const int*   __restrict__ idx,
                            const float* __restrict__ W1,
                            float* __restrict__ out) {
    const int gi = blockIdx.x * blockDim.x + threadIdx.x;
    if (gi >= PREP_TOTAL) return;
    if (gi < NSLOT) {
        const int e = idx[gi];
        const int p = atomicAdd(&g_cnt[e], 1);
        g_slots[e][p] = gi;
        return;
    }
    const int i = gi - NSLOT;
    if (i < NX4) {
        float4 v = ((const float4*)hidden)[i];
        ((__half2*)g_Xh)[2 * i + 0] = __floats2half2_rn(v.x, v.y);
        ((__half2*)g_Xh)[2 * i + 1] = __floats2half2_rn(v.z, v.w);
    } else if (i < NX4 + NWC) {
        // W1: KDIM=512, NT=8
        const int j  = i - NX4;
        const int e  = j >> 16;
        const int c  = j & 0xFFFF;
        const int nt = c >> 13;
        const int k  = (c >> 4) & 511;
        const int p  = c & 15;
        const int ch = p ^ (k & 7);
        const float* s = W1 + ((size_t)(e * 512 + k)) * F_DIM + nt * 128 + ch * 8;
        float4 v0 = *(const float4*)s, v1 = *(const float4*)(s + 4);
        uint4 o;
        o.x = f22h2(v0.x, v0.y); o.y = f22h2(v0.z, v0.w);
        o.z = f22h2(v1.x, v1.y); o.w = f22h2(v1.z, v1.w);
        *(uint4*)(g_W1p + ((size_t)((e * 8 + nt) * 512 + k)) * 128 + p * 8) = o;
    } else {
        int j = i - NX4 - NWC;
        ((float4*)out)[j] = make_float4(0.f, 0.f, 0.f, 0.f);
    }
}

// ---------------- W2 convert unit (queue head; MLP-8 unrolled) ----------------
// Unit u = (e, nt). Converts 16384 16B-chunks: dst[(e*4+nt)][k][p*8] = fp16 of
// W2[e*1024+k][nt*128 + (p^(k&7))*8]. 64 chunks/thread, unrolled x4 so 8
// independent float4 loads are in flight per iteration (hides DRAM latency).
__device__ void convert_w2_unit(int u, const float* __restrict__ W2, int tid) {
    const int e = u >> 2, nt = u & 3;
    const float* __restrict__ srcb = W2 + (size_t)e * F_DIM * D_DIM + nt * 128;
    __half* __restrict__ dstb = g_W2p + (size_t)(e * 4 + nt) * F_DIM * 128;
    #pragma unroll 1
    for (int it = 0; it < 16; ++it) {
        float4 v[4][2];
        int kk[4], pp[4];
        #pragma unroll
        for (int uu = 0; uu < 4; ++uu) {
            const int j = (it * 4 + uu) * NTHREADS + tid;
            const int k = j >> 4, p = j & 15, ch = p ^ (k & 7);
            kk[uu] = k; pp[uu] = p;
            const float* s = srcb + (size_t)k * D_DIM + ch * 8;
            v[uu][0] = *(const float4*)s;
            v[uu][1] = *(const float4*)(s + 4);
        }
        #pragma unroll
        for (int uu = 0; uu < 4; ++uu) {
            uint4 o;
            o.x = f22h2(v[uu][0].x, v[uu][0].y); o.y = f22h2(v[uu][0].z, v[uu][0].w);
            o.z = f22h2(v[uu][1].x, v[uu][1].y); o.w = f22h2(v[uu][1].z, v[uu][1].w);
            *(uint4*)(dstb + (size_t)kk[uu] * 128 + pp[uu] * 8) = o;
        }
    }
    __threadfence();
    __syncthreads();
    if (tid == 0) ready_release_inc(&g_w2rdy[u]);
}

// ---------------- one pipeline load step ----------------
// Dependency spins happen BEFORE the B bulk issue (B = g_W2p is guarded for p2).
__device__ __forceinline__ void load_step(
    int phase, const int* __restrict__ srow, const __half* __restrict__ Wtile,
    int kt, int pos, uint32_t sbase, uint32_t bbase0, uint64_t* s_mbar,
    int tid, const unsigned* ready_ptr, const unsigned* w2_ptr)
{
    const int s = pos % NSTAGE;
    const int k0 = kt * BK;
    if (ready_ptr) {
        while (ready_acquire_ld(ready_ptr) < (unsigned)(F_DIM / BN)) __nanosleep(64);
    }
    if (w2_ptr) {
        while (ready_acquire_ld(w2_ptr) == 0u) __nanosleep(64);
    }
    if (tid == 0) {
        const uint32_t mb = smem_u32(&s_mbar[s]);
        mbar_expect_tx(mb, B_STAGE_BYTES);
        cp_bulk(bbase0 + (uint32_t)s * B_STAGE_BYTES,
                Wtile + (size_t)k0 * 128, B_STAGE_BYTES, mb);
    }
    const uint32_t abuf = sbase + (uint32_t)s * A_STAGE_BYTES;
    #pragma unroll
    for (int it = 0; it < 4; ++it) {
        const int c  = tid + it * NTHREADS;
        const int r  = c >> 3;
        const int ch = c & 7;
        const int slot = srow[r];
        const __half* asrc = (phase == 1)
            ? g_Xh + (size_t)(slot >> 1) * D_DIM + k0 + ch * 8
            : g_H  + (size_t)slot * F_DIM        + k0 + ch * 8;
        cp_async16(abuf + (uint32_t)(r * 128 + ((ch ^ (r & 7)) << 4)), asrc);
    }
    cp_commit();
}

// ---------------- fused persistent GEMM + in-queue W2 conversion ----------------
// global work index: [0, NW2U) = W2 convert units; then p1 tiles; then p2 tiles.
__global__ __launch_bounds__(NTHREADS, 2)
void moe_gemm_fused(const float* __restrict__ b1,
                    const float* __restrict__ b2,
                    const float* __restrict__ wts,
                    const float* __restrict__ W2,
                    float* __restrict__ out) {
    extern __shared__ __align__(1024) char dsm[];
    const uint32_t sbase  = smem_u32(dsm);
    const uint32_t bbase0 = sbase + NSTAGE * A_STAGE_BYTES;

    __shared__ int      s_srow[2][BM];
    __shared__ uint64_t s_mbar[NSTAGE];
    __shared__ int      s_nxt;
    __shared__ int      s_tcnt[E_NUM], s_tb1[E_NUM];
    __shared__ int      s_p1tot;

    const int tid  = threadIdx.x;
    const int wid  = tid >> 5;
    const int lane = tid & 31;
    const int wm = (wid & 1) * 64;
    const int wn = (wid >> 1) * 32;
    const int rA = lane & 15;
    const int cl = lane >> 4;

    if (tid == 0) {
        #pragma unroll
        for (int s = 0; s < NSTAGE; ++s) mbar_init(smem_u32(&s_mbar[s]), 1);
        int acc = 0;
        #pragma unroll
        for (int e = 0; e < E_NUM; ++e) {
            s_tb1[e] = acc;
            int c = g_cnt[e];
            s_tcnt[e] = c;
            acc += ((c + BM - 1) >> 7) * (F_DIM / BN);
        }
        s_p1tot = acc;
    }
    __syncthreads();
    const int p1_total  = s_p1tot;
    const int total_all = NW2U + p1_total + (p1_total >> 1);

    // loop-invariant LDSM fragment offsets
    uint32_t offA[4][4], offB[4][2];
    #pragma unroll
    for (int mf = 0; mf < 4; ++mf) {
        const int r = wm + mf * 16 + rA;
        #pragma unroll
        for (int ks = 0; ks < 4; ++ks)
            offA[mf][ks] = (uint32_t)(r * 128 + (((ks * 2 + cl) ^ (r & 7)) << 4));
    }
    #pragma unroll
    for (int ks = 0; ks < 4; ++ks) {
        const int rb = ks * 16 + rA;
        #pragma unroll
        for (int nf16 = 0; nf16 < 2; ++nf16)
            offB[ks][nf16] = (uint32_t)(rb * 256 +
                              ((((wn >> 3) + nf16 * 2 + cl) ^ (rb & 7)) << 4));
    }

    // decode GEMM tile index tt (= global index - NW2U)
    auto decode = [&](int tt, int& phase, int& e, int& cnt, int& m0, int& nt) {
        if (tt < p1_total) {
            phase = 1; e = 0;
            #pragma unroll
            for (int q = 1; q < E_NUM; ++q) if (tt >= s_tb1[q]) e = q;
            const int local = tt - s_tb1[e];
            cnt = s_tcnt[e]; m0 = (local >> 3) << 7; nt = local & 7;
        } else {
            phase = 2; const int t2 = tt - p1_total; e = 0;
            #pragma unroll
            for (int q = 1; q < E_NUM; ++q) if (t2 >= (s_tb1[q] >> 1)) e = q;
            const int local = t2 - (s_tb1[e] >> 1);
            cnt = s_tcnt[e]; m0 = (local >> 2) << 7; nt = local & 3;
        }
    };
    auto wptr = [&](int phase, int e, int nt) -> const __half* {
        return (phase == 1)
            ? g_W1p + (size_t)(e * 8 + nt) * D_DIM * 128
            : g_W2p + (size_t)(e * 4 + nt) * F_DIM * 128;
    };

    // ----- initial work claim: CTAs 0..NW2U-1 convert W2 first -----
    int t0 = (int)blockIdx.x;
    while (t0 < NW2U) {
        convert_w2_unit(t0, W2, tid);
        if (tid == 0) s_nxt = atomicAdd(&g_work, 1);   // g_work starts at NCTA > NW2U
        __syncthreads();
        t0 = s_nxt;
        __syncthreads();
    }

    if (t0 < total_all) {
        int cphase, ce, ccnt, cm0, cnt_i;
        decode(t0 - NW2U, cphase, ce, ccnt, cm0, cnt_i);
        const __half* cW = wptr(cphase, ce, cnt_i);
        int curbuf = 0;

        if (tid < BM) s_srow[0][tid] = g_slots[ce][min(cm0 + tid, ccnt - 1)];
        __syncthreads();

        {
            const unsigned* rp0 = (cphase == 2)
                ? &g_ready[ce * MT_MAX + (cm0 >> 7)] : nullptr;
            const unsigned* w20 = (cphase == 2)
                ? &g_w2rdy[ce * 4 + cnt_i] : nullptr;
            load_step(cphase, s_srow[0], cW, 0, 0, sbase, bbase0, s_mbar, tid, rp0, w20);
            load_step(cphase, s_srow[0], cW, 1, 1, sbase, bbase0, s_mbar, tid, nullptr, nullptr);
        }

        int rc = 0;

        for (;;) {
            const int KT = (cphase == 1) ? KT1 : KT2;
            int nphase = 0, ne = 0, ncnt = 0, nm0 = 0, nnt = 0;
            bool have_nxt = false;
            const __half* nW = nullptr;

            float acc[4][4][4];
            #pragma unroll
            for (int i = 0; i < 4; ++i)
                #pragma unroll
                for (int j = 0; j < 4; ++j)
                    #pragma unroll
                    for (int r = 0; r < 4; ++r) acc[i][j][r] = 0.f;

            for (int kt = 0; kt < KT; ++kt) {
                const int s = rc % NSTAGE;
                cp_wait<1>();
                mbar_wait(smem_u32(&s_mbar[s]), (rc / NSTAGE) & 1);
                __syncthreads();

                if (kt == 0) {
                    if (tid == 0) s_nxt = atomicAdd(&g_work, 1);
                } else if (kt == 1) {
                    const int t = s_nxt;
                    have_nxt = t < total_all;
                    if (have_nxt) {
                        decode(t - NW2U, nphase, ne, ncnt, nm0, nnt);
                        nW = wptr(nphase, ne, nnt);
                        if (tid < BM)
                            s_srow[curbuf ^ 1][tid] = g_slots[ne][min(nm0 + tid, ncnt - 1)];
                    }
                }

                const uint32_t abuf = sbase + (uint32_t)s * A_STAGE_BYTES;
                const uint32_t bbuf = bbase0 + (uint32_t)s * B_STAGE_BYTES;

                #pragma unroll
                for (int ks = 0; ks < BK / 16; ++ks) {
                    uint32_t af[4][4];
                    #pragma unroll
                    for (int mf = 0; mf < 4; ++mf)
                        ldsm_x4(af[mf], abuf + offA[mf][ks]);
                    uint32_t bf[2][4];
                    #pragma unroll
                    for (int nf16 = 0; nf16 < 2; ++nf16)
                        ldsm_x4_trans(bf[nf16], bbuf + offB[ks][nf16]);
                    #pragma unroll
                    for (int mf = 0; mf < 4; ++mf)
                        #pragma unroll
                        for (int nf = 0; nf < 4; ++nf) {
                            const int g = nf >> 1;
                            const int h = (nf & 1) * 2;
                            mma_fp16(acc[mf][nf], af[mf], bf[g][h], bf[g][h + 1]);
                        }
                }

                // produce ring position rc+2 (after compute — R10 ordering)
                const int j2 = kt + 2;
                if (j2 < KT) {
                    load_step(cphase, s_srow[curbuf], cW, j2, rc + 2,
                              sbase, bbase0, s_mbar, tid, nullptr, nullptr);
                } else if (have_nxt && !(cphase == 1 && nphase == 2)) {
                    const bool first = (j2 - KT) == 0;
                    const unsigned* rp = (nphase == 2 && first)
                        ? &g_ready[ne * MT_MAX + (nm0 >> 7)] : nullptr;
                    const unsigned* w2 = (nphase == 2 && first)
                        ? &g_w2rdy[ne * 4 + nnt] : nullptr;
                    load_step(nphase, s_srow[curbuf ^ 1], nW, j2 - KT, rc + 2,
                              sbase, bbase0, s_mbar, tid, rp, w2);
                } else {
                    cp_commit();   // empty group keeps cp accounting uniform
                }
                ++rc;
            }

            // ---------------- epilogue ----------------
            {
                const int NDIM = (cphase == 1) ? F_DIM : D_DIM;
                const int n0   = cnt_i * BN;
                const float* __restrict__ brow =
                    ((cphase == 1) ? b1 : b2) + (size_t)ce * NDIM + n0;
                const int rbase = wm + (lane >> 2);
                const int cbase = wn + 2 * (lane & 3);
                #pragma unroll
                for (int mf = 0; mf < 4; ++mf) {
                    #pragma unroll
                    for (int half = 0; half < 2; ++half) {
                        const int rloc = rbase + mf * 16 + half * 8;
                        const int gm   = cm0 + rloc;
                        if (gm < ccnt) {
                            const int slot = s_srow[curbuf][rloc];
                            if (cphase == 1) {
                                __half* __restrict__ orow = g_H + (size_t)slot * F_DIM + n0;
                                #pragma unroll
                                for (int nf = 0; nf < 4; ++nf) {
                                    const int col = cbase + nf * 8;
                                    const float2 bv = *(const float2*)(brow + col);
                                    float v0 = gelu_fast(acc[mf][nf][half * 2 + 0] + bv.x);
                                    float v1 = gelu_fast(acc[mf][nf][half * 2 + 1] + bv.y);
                                    *(__half2*)(orow + col) = __floats2half2_rn(v0, v1);
                                }
                            } else {
                                const float w = __ldg(wts + slot);
                                float* __restrict__ orow =
                                    out + (size_t)(slot >> 1) * D_DIM + n0;
                                #pragma unroll
                                for (int nf = 0; nf < 4; ++nf) {
                                    const int col = cbase + nf * 8;
                                    const float2 bv = *(const float2*)(brow + col);
                                    float v0 = (acc[mf][nf][half * 2 + 0] + bv.x) * w;
                                    float v1 = (acc[mf][nf][half * 2 + 1] + bv.y) * w;
                                    red_add_v2(orow + col, v0, v1);
                                }
                            }
                        }
                    }
                }
            }

            if (cphase == 1) {
                __threadfence();
                __syncthreads();
                if (tid == 0) ready_release_inc(&g_ready[ce * MT_MAX + (cm0 >> 7)]);
            } else {
                // per-entry self-reset by the 4th (last) consumer
                if (tid == 0) {
                    const int ridx = ce * MT_MAX + (cm0 >> 7);
                    if (atomicAdd(&g_done[ridx], 1u) == 3u) {
                        g_ready[ridx] = 0u;
                        g_done[ridx]  = 0u;
                    }
                }
            }

            if (!have_nxt) break;

            if (cphase == 1 && nphase == 2) {
                const unsigned* rp = &g_ready[ne * MT_MAX + (nm0 >> 7)];
                const unsigned* w2 = &g_w2rdy[ne * 4 + nnt];
                load_step(nphase, s_srow[curbuf ^ 1], nW, 0, rc,
                          sbase, bbase0, s_mbar, tid, rp, w2);
                load_step(nphase, s_srow[curbuf ^ 1], nW, 1, rc + 1,
                          sbase, bbase0, s_mbar, tid, nullptr, nullptr);
            }

            cphase = nphase; ce = ne; ccnt = ncnt; cm0 = nm0; cnt_i = nnt;
            cW = nW; curbuf ^= 1;
        }
    }

    // self-reset of g_cnt / g_work / g_w2rdy for the next graph replay.
    __syncthreads();
    if (tid == 0) {
        if (atomicAdd(&g_exit, 1) == NCTA - 1) {
            #pragma unroll
            for (int e = 0; e < E_NUM; ++e) g_cnt[e] = 0;
            #pragma unroll
            for (int u = 0; u < NW2U; ++u) g_w2rdy[u] = 0u;
            g_work = NCTA;
            g_exit = 0;
        }
    }
}

// ---------------- launch (2 kernels, plain launches) ----------------
extern "C" void kernel_launch(void* const* d_in, const int* in_sizes, int n_in,
                              void* d_out, int out_size) {
    const float* hidden = (const float*)d_in[0];
    const int*   idx    = (const int*)d_in[1];
    const float* wts    = (const float*)d_in[2];
    const float* W1     = (const float*)d_in[3];
    const float* b1     = (const float*)d_in[4];
    const float* W2     = (const float*)d_in[5];
    const float* b2     = (const float*)d_in[6];
    float*       out    = (float*)d_out;
    (void)in_sizes; (void)n_in; (void)out_size;

    cudaFuncSetAttribute(moe_gemm_fused, cudaFuncAttributeMaxDynamicSharedMemorySize, SMEM_BYTES);

    prep_kernel<<<(PREP_TOTAL + 255) / 256, 256>>>(hidden, idx, W1, out);
    moe_gemm_fused<<<NCTA, NTHREADS, SMEM_BYTES>>>(b1, b2, wts, W2, out);
}